// round 3
// baseline (speedup 1.0000x reference)
#include <cuda_runtime.h>
#include <math.h>

#define MTOK 16384
#define DDIM 1024
#define CCLS 1000
#define LNUM 6
#define NBR  3
#define SDIM 64
#define KTOP 204
#define THRC 0.85f

// ---------------- scratch (device globals; no allocations allowed) ----------------
__device__ float g_x[MTOK * DDIM];                 // 64 MB  current hidden state
__device__ float g_h[MTOK * DDIM];                 // 64 MB  DCA layer output
__device__ float g_sims[NBR * MTOK * DDIM];        // 192 MB CEN branch sims
__device__ unsigned char g_active[MTOK];
__device__ int g_depth[MTOK];
__device__ float g_scores[NBR];
__device__ int g_best;
__device__ double g_vloss;

__device__ __forceinline__ float gelu_exact(float v) {
    return 0.5f * v * (1.0f + erff(v * 0.70710678118654752440f));
}

// packed fp32x2 FMA: two independent fp32 FMAs per issue slot, same rounding as fmaf
#define FMA2(c, a, b) asm("fma.rn.f32x2 %0, %1, %2, %0;" : "+l"(c) : "l"(a), "l"(b))
#define DUP2(d, v) do { unsigned _u = __float_as_uint(v); \
    asm("mov.b64 %0, {%1, %1};" : "=l"(d) : "r"(_u)); } while (0)
#define PACK2(d, lo, hi) do { unsigned _a = __float_as_uint(lo), _b = __float_as_uint(hi); \
    asm("mov.b64 %0, {%1, %2};" : "=l"(d) : "r"(_a), "r"(_b)); } while (0)

__device__ __forceinline__ float2 u2f2(unsigned long long v) {
    float2 r;
    r.x = __uint_as_float((unsigned)(v & 0xffffffffull));
    r.y = __uint_as_float((unsigned)(v >> 32));
    return r;
}

// ---------------- init: copy x, reset state ----------------
__global__ void init_kernel(const float* __restrict__ x) {
    int tid = blockIdx.x * blockDim.x + threadIdx.x;
    int stride = gridDim.x * blockDim.x;
    const float4* x4 = (const float4*)x;
    float4* g4 = (float4*)g_x;
    for (int i = tid; i < MTOK * DDIM / 4; i += stride) g4[i] = x4[i];
    for (int i = tid; i < MTOK; i += stride) { g_active[i] = 1; g_depth[i] = 0; }
    if (tid == 0) {
        g_vloss = 0.0; g_best = 0;
        g_scores[0] = 0.f; g_scores[1] = 0.f; g_scores[2] = 0.f;
    }
}

// ---------------- fp32 SGEMM via packed FFMA2: C = act(A[M,K] @ B[K,N] + bias) ----------------
// BM=BN=128, BK=16, 256 threads, 8x8 per thread. A tile stored DUPLICATED in smem so
// LDS.128 yields (a,a) pairs for fma.rn.f32x2 with zero pack cost. Accumulation order
// per output is identical to the scalar version (bitwise-identical results).
// ACT: 1 = exact GELU epilogue; 2 = plain epilogue, row-predicated by actmask.
#define ASTRIDE 260
template <int ACT>
__global__ __launch_bounds__(256) void sgemm_kernel(
    const float* __restrict__ A, const float* __restrict__ B,
    const float* __restrict__ bias, float* __restrict__ C,
    int M, int N, int K, const unsigned char* __restrict__ actmask)
{
    __shared__ float Asd[16][ASTRIDE];   // duplicated+transposed: row r at cols [2r,2r+1]
    __shared__ float Bs[16][128];

    const int tid = threadIdx.x;
    const int bx = blockIdx.x, by = blockIdx.y;
    const float* Ab = A + (size_t)by * 128 * K;

    const int trow = tid >> 4, tcol = tid & 15;

    const int ar0 = tid >> 2, ac0 = (tid & 3) * 4;   // A: 2 float4 per thread
    const int ar1 = ar0 + 64;
    const int bk0 = tid >> 5, bc0 = (tid & 31) * 4;  // B: 2 float4 per thread
    const int bk1 = bk0 + 8;
    const int gcolB = bx * 128 + bc0;
    const bool bok = (gcolB < N);
    const float* Bp = B + gcolB;

    unsigned long long acc2[8][4];
#pragma unroll
    for (int i = 0; i < 8; i++)
#pragma unroll
        for (int j = 0; j < 4; j++) acc2[i][j] = 0ull;

    float4 a0, a1, b0, b1;
    const float4 z4 = make_float4(0.f, 0.f, 0.f, 0.f);
    a0 = *(const float4*)(Ab + (size_t)ar0 * K + ac0);
    a1 = *(const float4*)(Ab + (size_t)ar1 * K + ac0);
    b0 = bok ? *(const float4*)(Bp + (size_t)bk0 * N) : z4;
    b1 = bok ? *(const float4*)(Bp + (size_t)bk1 * N) : z4;

    for (int k0 = 0; k0 < K; k0 += 16) {
        // duplicated stores: element (k=ac0+i, row r) -> Asd[ac0+i][2r..2r+1]
        *(float2*)&Asd[ac0 + 0][2 * ar0] = make_float2(a0.x, a0.x);
        *(float2*)&Asd[ac0 + 1][2 * ar0] = make_float2(a0.y, a0.y);
        *(float2*)&Asd[ac0 + 2][2 * ar0] = make_float2(a0.z, a0.z);
        *(float2*)&Asd[ac0 + 3][2 * ar0] = make_float2(a0.w, a0.w);
        *(float2*)&Asd[ac0 + 0][128 + 2 * ar0] = make_float2(a1.x, a1.x);
        *(float2*)&Asd[ac0 + 1][128 + 2 * ar0] = make_float2(a1.y, a1.y);
        *(float2*)&Asd[ac0 + 2][128 + 2 * ar0] = make_float2(a1.z, a1.z);
        *(float2*)&Asd[ac0 + 3][128 + 2 * ar0] = make_float2(a1.w, a1.w);
        *(float4*)&Bs[bk0][bc0] = b0;
        *(float4*)&Bs[bk1][bc0] = b1;
        __syncthreads();

        if (k0 + 16 < K) {
            a0 = *(const float4*)(Ab + (size_t)ar0 * K + (k0 + 16) + ac0);
            a1 = *(const float4*)(Ab + (size_t)ar1 * K + (k0 + 16) + ac0);
            b0 = bok ? *(const float4*)(Bp + (size_t)(k0 + 16 + bk0) * N) : z4;
            b1 = bok ? *(const float4*)(Bp + (size_t)(k0 + 16 + bk1) * N) : z4;
        }

#pragma unroll
        for (int kk = 0; kk < 16; kk++) {
            ulonglong2 aq0 = *(const ulonglong2*)&Asd[kk][8 * trow];          // (a0,a0),(a1,a1)
            ulonglong2 aq1 = *(const ulonglong2*)&Asd[kk][8 * trow + 4];      // (a2,a2),(a3,a3)
            ulonglong2 aq2 = *(const ulonglong2*)&Asd[kk][128 + 8 * trow];
            ulonglong2 aq3 = *(const ulonglong2*)&Asd[kk][128 + 8 * trow + 4];
            ulonglong2 bq0 = *(const ulonglong2*)&Bs[kk][tcol * 4];           // (b0,b1),(b2,b3)
            ulonglong2 bq1 = *(const ulonglong2*)&Bs[kk][64 + tcol * 4];
            unsigned long long av[8] = {aq0.x, aq0.y, aq1.x, aq1.y,
                                        aq2.x, aq2.y, aq3.x, aq3.y};
            unsigned long long bv[4] = {bq0.x, bq0.y, bq1.x, bq1.y};
#pragma unroll
            for (int i = 0; i < 8; i++)
#pragma unroll
                for (int j = 0; j < 4; j++) FMA2(acc2[i][j], av[i], bv[j]);
        }
        __syncthreads();
    }

#pragma unroll
    for (int i = 0; i < 8; i++) {
        int row = by * 128 + ((i < 4) ? (trow * 4 + i) : (64 + trow * 4 + (i - 4)));
        bool rowok = true;
        if (ACT == 2) rowok = (actmask[row] != 0);
        if (!rowok) continue;
#pragma unroll
        for (int jq = 0; jq < 2; jq++) {
            int col = bx * 128 + (jq ? (64 + tcol * 4) : (tcol * 4));
            if (col < N) {
                float2 p0 = u2f2(acc2[i][jq * 2 + 0]);
                float2 p1 = u2f2(acc2[i][jq * 2 + 1]);
                float v0 = p0.x + bias[col + 0];
                float v1 = p0.y + bias[col + 1];
                float v2 = p1.x + bias[col + 2];
                float v3 = p1.y + bias[col + 3];
                if (ACT == 1) {
                    v0 = gelu_exact(v0); v1 = gelu_exact(v1);
                    v2 = gelu_exact(v2); v3 = gelu_exact(v3);
                }
                *(float4*)(C + (size_t)row * N + col) = make_float4(v0, v1, v2, v3);
            }
        }
    }
}

// ---------------- per-token exact top-K select + masked residual add ----------------
__global__ void topk_kernel() {
    int row = blockIdx.x;
    int tid = threadIdx.x;
    __shared__ float sh[DDIM];
    __shared__ int hist[256];
    __shared__ int s_k;
    __shared__ unsigned s_pref;

    const float* hr = g_h + (size_t)row * DDIM;
    for (int j = tid; j < DDIM; j += 256) sh[j] = hr[j];
    if (tid == 0) { s_k = KTOP; s_pref = 0u; }
    __syncthreads();

    for (int shift = 24; shift >= 0; shift -= 8) {
        hist[tid] = 0;
        __syncthreads();
        unsigned pref = s_pref;
        for (int j = tid; j < DDIM; j += 256) {
            unsigned b = __float_as_uint(fabsf(sh[j]));
            bool cand = (shift == 24) || ((b >> (shift + 8)) == pref);
            if (cand) atomicAdd(&hist[(b >> shift) & 255], 1);
        }
        __syncthreads();
        if (tid == 0) {
            int k = s_k, cum = 0, d = 255;
            for (; d >= 0; --d) { cum += hist[d]; if (cum >= k) break; }
            s_k = k - (cum - hist[d]);
            s_pref = (pref << 8) | (unsigned)d;
        }
        __syncthreads();
    }
    unsigned kbits = s_pref;
    if (g_active[row]) {
        float* xr = g_x + (size_t)row * DDIM;
        for (int j = tid; j < DDIM; j += 256) {
            unsigned b = __float_as_uint(fabsf(sh[j]));
            if (b >= kbits) xr[j] += sh[j];
        }
    }
}

// ---------------- CEN ----------------
__global__ void cen_score_kernel(const float* __restrict__ cohW,
                                 const float* __restrict__ cohb) {
    int row = blockIdx.x;
    if (!g_active[row]) return;
    int tid = threadIdx.x;
    __shared__ float red[256];
    float cb = cohb[0];
    for (int n = 0; n < NBR; n++) {
        const float* sr = g_sims + ((size_t)n * MTOK + row) * DDIM;
        float p = 0.f;
        for (int j = tid; j < DDIM; j += 256) p += sr[j] * cohW[j];
        red[tid] = p; __syncthreads();
        for (int s = 128; s > 0; s >>= 1) {
            if (tid < s) red[tid] += red[tid + s];
            __syncthreads();
        }
        if (tid == 0) atomicAdd(&g_scores[n], red[0] + cb);
        __syncthreads();
    }
}

__global__ void argmax_kernel() {
    if (threadIdx.x == 0) {
        int b = 0; float v = g_scores[0];
        if (g_scores[1] > v) { b = 1; v = g_scores[1]; }
        if (g_scores[2] > v) { b = 2; }
        g_best = b;
    }
}

__global__ void cen_add_kernel() {
    int best = g_best;
    const float4* s4 = (const float4*)(g_sims + (size_t)best * MTOK * DDIM);
    float4* x4 = (float4*)g_x;
    int tid = blockIdx.x * blockDim.x + threadIdx.x;
    int stride = gridDim.x * blockDim.x;
    for (int i = tid; i < MTOK * DDIM / 4; i += stride) {
        int row = i >> 8;
        if (g_active[row]) {
            float4 a = x4[i]; float4 b = s4[i];
            a.x += b.x; a.y += b.y; a.z += b.z; a.w += b.w;
            x4[i] = a;
        }
    }
}

// ---------------- fused VLM autoencoder loss ----------------
// 32 tokens/block, 256 threads. enc: thread = (token t = tid>>3, sd-octet o = tid&7);
// each LDS of x is a broadcast feeding 8 FMAs. dec: thread owns j-quad = tid*4, tiles
// tokens by 8; hid LDS are block-wide broadcasts. FFMA2 in both phases.
__global__ __launch_bounds__(256) void vlm_kernel(
    const float* __restrict__ encW, const float* __restrict__ encb,
    const float* __restrict__ decW, const float* __restrict__ decb)
{
    __shared__ float xs[32][132];
    __shared__ float shid[32][65];
    __shared__ float red[256];
    const int t0 = blockIdx.x * 32;
    const int tid = threadIdx.x;
    const int t = tid >> 3, o = tid & 7;

    // ---- encoder ----
    unsigned long long eacc[4];
#pragma unroll
    for (int p = 0; p < 4; p++)
        PACK2(eacc[p], encb[o * 8 + 2 * p], encb[o * 8 + 2 * p + 1]);

    for (int kc = 0; kc < DDIM; kc += 128) {
        __syncthreads();
        for (int e = tid; e < 32 * 128; e += 256) {
            int tt = e >> 7, kk = e & 127;
            xs[tt][kk] = g_x[(size_t)(t0 + tt) * DDIM + kc + kk];
        }
        __syncthreads();
        for (int k = 0; k < 128; k++) {
            unsigned long long xd;
            DUP2(xd, xs[t][k]);
            ulonglong2 w01 = *(const ulonglong2*)&encW[(size_t)(kc + k) * SDIM + o * 8];
            ulonglong2 w23 = *(const ulonglong2*)&encW[(size_t)(kc + k) * SDIM + o * 8 + 4];
            FMA2(eacc[0], xd, w01.x);
            FMA2(eacc[1], xd, w01.y);
            FMA2(eacc[2], xd, w23.x);
            FMA2(eacc[3], xd, w23.y);
        }
    }
#pragma unroll
    for (int p = 0; p < 4; p++) {
        float2 v = u2f2(eacc[p]);
        shid[t][o * 8 + 2 * p + 0] = fmaxf(v.x, 0.f);
        shid[t][o * 8 + 2 * p + 1] = fmaxf(v.y, 0.f);
    }
    __syncthreads();

    // ---- decoder + squared error ----
    const int j0 = tid * 4;
    unsigned long long bias2[2];
    PACK2(bias2[0], decb[j0 + 0], decb[j0 + 1]);
    PACK2(bias2[1], decb[j0 + 2], decb[j0 + 3]);

    float sq = 0.f;
    for (int tt = 0; tt < 4; tt++) {
        unsigned long long acc2[8][2];
#pragma unroll
        for (int u = 0; u < 8; u++) { acc2[u][0] = bias2[0]; acc2[u][1] = bias2[1]; }
        for (int s = 0; s < SDIM; s++) {
            ulonglong2 wv = *(const ulonglong2*)&decW[(size_t)s * DDIM + j0];
            unsigned long long hd[8];
#pragma unroll
            for (int u = 0; u < 8; u++) DUP2(hd[u], shid[tt * 8 + u][s]);
#pragma unroll
            for (int u = 0; u < 8; u++) {
                FMA2(acc2[u][0], hd[u], wv.x);
                FMA2(acc2[u][1], hd[u], wv.y);
            }
        }
#pragma unroll
        for (int u = 0; u < 8; u++) {
            float4 xv = *(const float4*)&g_x[(size_t)(t0 + tt * 8 + u) * DDIM + j0];
            float2 r0 = u2f2(acc2[u][0]);
            float2 r1 = u2f2(acc2[u][1]);
            float d0 = r0.x - xv.x, d1 = r0.y - xv.y;
            float d2 = r1.x - xv.z, d3 = r1.y - xv.w;
            sq = fmaf(d0, d0, sq); sq = fmaf(d1, d1, sq);
            sq = fmaf(d2, d2, sq); sq = fmaf(d3, d3, sq);
        }
    }
    red[tid] = sq; __syncthreads();
    for (int s = 128; s > 0; s >>= 1) {
        if (tid < s) red[tid] += red[tid + s];
        __syncthreads();
    }
    if (tid == 0) atomicAdd(&g_vloss, (double)red[0]);
}

// ---------------- exit head: conf from d_out (active rows), update depth/active ----------------
__global__ void exit_kernel(const float* __restrict__ out) {
    int row = blockIdx.x;
    if (!g_active[row]) return;
    int tid = threadIdx.x;
    const float* lr = out + (size_t)row * CCLS;
    __shared__ float red[256];

    float mx = -1e30f;
    for (int j = tid; j < CCLS; j += 256) mx = fmaxf(mx, lr[j]);
    red[tid] = mx; __syncthreads();
    for (int s = 128; s > 0; s >>= 1) {
        if (tid < s) red[tid] = fmaxf(red[tid], red[tid + s]);
        __syncthreads();
    }
    float m = red[0]; __syncthreads();

    float se = 0.f;
    for (int j = tid; j < CCLS; j += 256) se += expf(lr[j] - m);
    red[tid] = se; __syncthreads();
    for (int s = 128; s > 0; s >>= 1) {
        if (tid < s) red[tid] += red[tid + s];
        __syncthreads();
    }
    float conf = 1.0f / red[0];

    if (tid == 0) {
        g_depth[row]++;
        g_active[row] = (conf < THRC) ? 1 : 0;
    }
}

// ---------------- finalize scalars ----------------
__global__ void finalize_kernel(float* __restrict__ out, int base) {
    __shared__ int red[256];
    int tid = threadIdx.x;
    int s = 0;
    for (int i = tid; i < MTOK; i += 256) s += g_depth[i];
    red[tid] = s; __syncthreads();
    for (int w = 128; w > 0; w >>= 1) {
        if (tid < w) red[tid] += red[tid + w];
        __syncthreads();
    }
    if (tid == 0) {
        out[base + 0] = (float)red[0] / (float)MTOK;
        out[base + 1] = (float)(g_vloss / ((double)LNUM * (double)MTOK * (double)DDIM));
    }
}

// ---------------- host orchestration ----------------
extern "C" void kernel_launch(void* const* d_in, const int* in_sizes, int n_in,
                              void* d_out, int out_size) {
    const float* x    = (const float*)d_in[0];
    const float* dcaW = (const float*)d_in[1];
    const float* dcab = (const float*)d_in[2];
    const float* exW  = (const float*)d_in[3];
    const float* exb  = (const float*)d_in[4];
    const float* cenW = (const float*)d_in[5];
    const float* cenb = (const float*)d_in[6];
    const float* cohW = (const float*)d_in[7];
    const float* cohb = (const float*)d_in[8];
    const float* encW = (const float*)d_in[9];
    const float* encb = (const float*)d_in[10];
    const float* decW = (const float*)d_in[11];
    const float* decb = (const float*)d_in[12];
    float* out = (float*)d_out;

    float *px, *ph, *ps;
    unsigned char* pact;
    cudaGetSymbolAddress((void**)&px, g_x);
    cudaGetSymbolAddress((void**)&ph, g_h);
    cudaGetSymbolAddress((void**)&ps, g_sims);
    cudaGetSymbolAddress((void**)&pact, g_active);

    init_kernel<<<2048, 256>>>(x);

    dim3 gD(DDIM / 128, MTOK / 128);           // (8,128) N=1024
    dim3 gC((CCLS + 127) / 128, MTOK / 128);   // (8,128) N=1000

    for (int i = 0; i < LNUM; i++) {
        // SparseDCA: h = gelu(x @ dca_W[i] + dca_b[i])
        sgemm_kernel<1><<<gD, 256>>>(px, dcaW + (size_t)i * DDIM * DDIM,
                                     dcab + (size_t)i * DDIM, ph, MTOK, DDIM, DDIM,
                                     (const unsigned char*)0);
        topk_kernel<<<MTOK, 256>>>();

        if (i == LNUM / 2) {
            for (int n = 0; n < NBR; n++) {
                sgemm_kernel<1><<<gD, 256>>>(px, cenW + (size_t)n * DDIM * DDIM,
                                             cenb + (size_t)n * DDIM,
                                             ps + (size_t)n * MTOK * DDIM,
                                             MTOK, DDIM, DDIM, (const unsigned char*)0);
            }
            cen_score_kernel<<<MTOK, 256>>>(cohW, cohb);
            argmax_kernel<<<1, 32>>>();
            cen_add_kernel<<<4096, 256>>>();
        }

        // VLM vicarious loss on current x
        vlm_kernel<<<MTOK / 32, 256>>>(encW, encb, decW, decb);

        // exit head logits: active rows written straight into d_out
        sgemm_kernel<2><<<gC, 256>>>(px, exW + (size_t)i * DDIM * CCLS,
                                     exb + (size_t)i * CCLS, out, MTOK, CCLS, DDIM, pact);
        exit_kernel<<<MTOK, 256>>>(out);
    }

    finalize_kernel<<<1, 256>>>(out, out_size - 2);
}

// round 12
// speedup vs baseline: 1.1631x; 1.1631x over previous
#include <cuda_runtime.h>
#include <math.h>
#include <stdint.h>

#define MTOK 16384
#define DDIM 1024
#define CCLS 1000
#define LNUM 6
#define NBR  3
#define SDIM 64
#define KTOP 204
#define THRC 0.85f

// TC GEMM tiling: 128x128x16, warp grid 4(m) x 2(n)
#define BM 128
#define BN 128
#define BK 16
#define PAD 136

__device__ float g_x[MTOK * DDIM];     // 64 MB
__device__ float g_h[MTOK * DDIM];     // 64 MB
__device__ unsigned char g_active[MTOK];
__device__ int g_depth[MTOK];
__device__ float g_scores[NBR];
__device__ int g_best;
__device__ double g_vloss;

__device__ __forceinline__ float gelu_exact(float v) {
    return 0.5f * v * (1.0f + erff(v * 0.70710678118654752440f));
}
// Veltkamp split to tf32 (ran in R11): hi = rna_tf32(v), lo = rna_tf32(v - hi)
__device__ __forceinline__ void tf32_split(float v, unsigned& h, unsigned& l) {
    float t = __fmul_rn(v, 8193.0f);
    float hf = __fsub_rn(t, __fsub_rn(t, v));
    h = __float_as_uint(hf);
    unsigned lo;
    asm("cvt.rna.tf32.f32 %0, %1;" : "=r"(lo) : "f"(__fsub_rn(v, hf)));
    l = lo;
}
#define MMA(d, a, b) asm volatile( \
    "mma.sync.aligned.m16n8k8.row.col.f32.tf32.tf32.f32 " \
    "{%0,%1,%2,%3}, {%4,%5,%6,%7}, {%8,%9}, {%0,%1,%2,%3};" \
    : "+f"((d)[0]), "+f"((d)[1]), "+f"((d)[2]), "+f"((d)[3]) \
    : "r"((a)[0]), "r"((a)[1]), "r"((a)[2]), "r"((a)[3]), "r"((b)[0]), "r"((b)[1]))

__global__ void init_kernel(const float* __restrict__ x) {
    int tid = blockIdx.x * blockDim.x + threadIdx.x, st = gridDim.x * blockDim.x;
    const float4* x4 = (const float4*)x;
    float4* g4 = (float4*)g_x;
    for (int i = tid; i < MTOK * DDIM / 4; i += st) g4[i] = x4[i];
    for (int i = tid; i < MTOK; i += st) { g_active[i] = 1; g_depth[i] = 0; }
    if (tid == 0) { g_vloss = 0.0; g_best = 0; g_scores[0] = g_scores[1] = g_scores[2] = 0.f; }
}

// ---------------- R1 scalar fp32 SGEMM (bitwise-identical trajectory) ----------------
// C = gelu(A@B + bias). Per-output accumulation: pure ascending-k fmaf chain.
// bestPtr != 0 -> CEN pass2 (offset B/bias by *bestPtr).
__global__ __launch_bounds__(256) void sgemm_kernel(
    const float* __restrict__ A, const float* __restrict__ B,
    const float* __restrict__ bias, float* __restrict__ C,
    int M, int N, int K, const int* __restrict__ bestPtr)
{
    __shared__ float As[16][132];
    __shared__ float Bs[16][128];

    if (bestPtr) {
        int b = *bestPtr;
        B += (size_t)b * DDIM * DDIM;
        bias += (size_t)b * DDIM;
    }

    const int tid = threadIdx.x;
    const int bx = blockIdx.x, by = blockIdx.y;
    const float* Ab = A + (size_t)by * 128 * K;
    const int trow = tid >> 4, tcol = tid & 15;
    const int ar0 = tid >> 2, ac0 = (tid & 3) * 4;
    const int ar1 = ar0 + 64;
    const int bk0 = tid >> 5, bc0 = (tid & 31) * 4;
    const int bk1 = bk0 + 8;
    const int gcolB = bx * 128 + bc0;
    const bool bok = (gcolB < N);
    const float* Bp = B + gcolB;

    float acc[8][8];
#pragma unroll
    for (int i = 0; i < 8; i++)
#pragma unroll
        for (int j = 0; j < 8; j++) acc[i][j] = 0.f;

    float4 a0, a1, b0, b1;
    const float4 z4 = make_float4(0.f, 0.f, 0.f, 0.f);
    a0 = *(const float4*)(Ab + (size_t)ar0 * K + ac0);
    a1 = *(const float4*)(Ab + (size_t)ar1 * K + ac0);
    b0 = bok ? *(const float4*)(Bp + (size_t)bk0 * N) : z4;
    b1 = bok ? *(const float4*)(Bp + (size_t)bk1 * N) : z4;

    for (int k0 = 0; k0 < K; k0 += 16) {
        As[ac0 + 0][ar0] = a0.x; As[ac0 + 1][ar0] = a0.y;
        As[ac0 + 2][ar0] = a0.z; As[ac0 + 3][ar0] = a0.w;
        As[ac0 + 0][ar1] = a1.x; As[ac0 + 1][ar1] = a1.y;
        As[ac0 + 2][ar1] = a1.z; As[ac0 + 3][ar1] = a1.w;
        *(float4*)&Bs[bk0][bc0] = b0;
        *(float4*)&Bs[bk1][bc0] = b1;
        __syncthreads();

        if (k0 + 16 < K) {
            a0 = *(const float4*)(Ab + (size_t)ar0 * K + (k0 + 16) + ac0);
            a1 = *(const float4*)(Ab + (size_t)ar1 * K + (k0 + 16) + ac0);
            b0 = bok ? *(const float4*)(Bp + (size_t)(k0 + 16 + bk0) * N) : z4;
            b1 = bok ? *(const float4*)(Bp + (size_t)(k0 + 16 + bk1) * N) : z4;
        }

#pragma unroll
        for (int kk = 0; kk < 16; kk++) {
            float4 ra0 = *(const float4*)&As[kk][trow * 4];
            float4 ra1 = *(const float4*)&As[kk][64 + trow * 4];
            float4 rb0 = *(const float4*)&Bs[kk][tcol * 4];
            float4 rb1 = *(const float4*)&Bs[kk][64 + tcol * 4];
            float ra[8] = {ra0.x, ra0.y, ra0.z, ra0.w, ra1.x, ra1.y, ra1.z, ra1.w};
            float rb[8] = {rb0.x, rb0.y, rb0.z, rb0.w, rb1.x, rb1.y, rb1.z, rb1.w};
#pragma unroll
            for (int i = 0; i < 8; i++)
#pragma unroll
                for (int j = 0; j < 8; j++) acc[i][j] = fmaf(ra[i], rb[j], acc[i][j]);
        }
        __syncthreads();
    }

#pragma unroll
    for (int i = 0; i < 8; i++) {
        int row = by * 128 + ((i < 4) ? (trow * 4 + i) : (64 + trow * 4 + (i - 4)));
#pragma unroll
        for (int jq = 0; jq < 2; jq++) {
            int col = bx * 128 + (jq ? (64 + tcol * 4) : (tcol * 4));
            if (col < N) {
                float v0 = gelu_exact(acc[i][jq * 4 + 0] + bias[col + 0]);
                float v1 = gelu_exact(acc[i][jq * 4 + 1] + bias[col + 1]);
                float v2 = gelu_exact(acc[i][jq * 4 + 2] + bias[col + 2]);
                float v3 = gelu_exact(acc[i][jq * 4 + 3] + bias[col + 3]);
                *(float4*)(C + (size_t)row * N + col) = make_float4(v0, v1, v2, v3);
            }
        }
    }
}

// ---------------- TC 3xTF32 mma.sync GEMM (flip-immune passes only) ----------------
// ACT 2: C = v+bias, rows with actmask!=0 only (exit head -> d_out)
// ACT 3: no store; atomicAdd(scorePtr, sum_{active rows} gelu(v+bias)*cohW[col])
template <int ACT>
__global__ __launch_bounds__(256) void mma_gemm(
    const float* __restrict__ A, const float* __restrict__ B,
    const float* __restrict__ bias, float* __restrict__ C, int N,
    const unsigned char* __restrict__ actmask,
    const float* __restrict__ cohW, float* __restrict__ scorePtr)
{
    __shared__ float As[BK][PAD];
    __shared__ float Bs[BK][PAD];
    __shared__ float red[256];

    const int tid = threadIdx.x;
    const int lane = tid & 31, wid = tid >> 5;
    const int wm = wid & 3, wn = wid >> 2;
    const int g = lane >> 2, tig = lane & 3;
    const int m0 = blockIdx.y * BM, n0 = blockIdx.x * BN;

    const int ar = tid >> 2, ac = (tid & 3) * 4;
    const int bk = tid >> 5, bc = (tid & 31) * 4;
    const int gcol = n0 + bc;
    const bool bok = (gcol + 3 < N);
    const float4 z4 = make_float4(0.f, 0.f, 0.f, 0.f);

    float acc[2][8][4];
#pragma unroll
    for (int i = 0; i < 2; i++)
#pragma unroll
        for (int j = 0; j < 8; j++)
#pragma unroll
            for (int q = 0; q < 4; q++) acc[i][j][q] = 0.f;

    float4 a0, a1, b0, b1;
    a0 = *(const float4*)(A + (size_t)(m0 + ar) * DDIM + ac);
    a1 = *(const float4*)(A + (size_t)(m0 + ar + 64) * DDIM + ac);
    b0 = bok ? *(const float4*)(B + (size_t)bk * N + gcol) : z4;
    b1 = bok ? *(const float4*)(B + (size_t)(bk + 8) * N + gcol) : z4;

    for (int kc = 0; kc < DDIM; kc += BK) {
        As[ac + 0][ar] = a0.x; As[ac + 1][ar] = a0.y;
        As[ac + 2][ar] = a0.z; As[ac + 3][ar] = a0.w;
        As[ac + 0][ar + 64] = a1.x; As[ac + 1][ar + 64] = a1.y;
        As[ac + 2][ar + 64] = a1.z; As[ac + 3][ar + 64] = a1.w;
        *(float4*)&Bs[bk][bc] = b0;
        *(float4*)&Bs[bk + 8][bc] = b1;
        __syncthreads();

        if (kc + BK < DDIM) {
            a0 = *(const float4*)(A + (size_t)(m0 + ar) * DDIM + kc + BK + ac);
            a1 = *(const float4*)(A + (size_t)(m0 + ar + 64) * DDIM + kc + BK + ac);
            b0 = bok ? *(const float4*)(B + (size_t)(kc + BK + bk) * N + gcol) : z4;
            b1 = bok ? *(const float4*)(B + (size_t)(kc + BK + bk + 8) * N + gcol) : z4;
        }

#pragma unroll
        for (int ks = 0; ks < 2; ks++) {
            const int kb = ks * 8;
            unsigned ah[2][4], al[2][4];
#pragma unroll
            for (int i = 0; i < 2; i++) {
                int r = wm * 32 + i * 16 + g;
                tf32_split(As[kb + tig][r],         ah[i][0], al[i][0]);
                tf32_split(As[kb + tig][r + 8],     ah[i][1], al[i][1]);
                tf32_split(As[kb + tig + 4][r],     ah[i][2], al[i][2]);
                tf32_split(As[kb + tig + 4][r + 8], ah[i][3], al[i][3]);
            }
#pragma unroll
            for (int j = 0; j < 8; j++) {
                int n = wn * 64 + j * 8 + g;
                unsigned bh[2], bl[2];
                tf32_split(Bs[kb + tig][n],     bh[0], bl[0]);
                tf32_split(Bs[kb + tig + 4][n], bh[1], bl[1]);
                MMA(acc[0][j], ah[0], bh);
                MMA(acc[0][j], ah[0], bl);
                MMA(acc[0][j], al[0], bh);
                MMA(acc[1][j], ah[1], bh);
                MMA(acc[1][j], ah[1], bl);
                MMA(acc[1][j], al[1], bh);
            }
        }
        __syncthreads();
    }

    if (ACT == 3) {
        float sacc = 0.f;
#pragma unroll
        for (int i = 0; i < 2; i++)
#pragma unroll
            for (int rr = 0; rr < 2; rr++) {
                int row = m0 + wm * 32 + i * 16 + g + rr * 8;
                if (!actmask[row]) continue;
#pragma unroll
                for (int j = 0; j < 8; j++) {
                    int c0 = n0 + wn * 64 + j * 8 + tig * 2;
                    sacc += gelu_exact(acc[i][j][rr * 2 + 0] + bias[c0]) * cohW[c0];
                    sacc += gelu_exact(acc[i][j][rr * 2 + 1] + bias[c0 + 1]) * cohW[c0 + 1];
                }
            }
        red[tid] = sacc;
        __syncthreads();
        for (int s = 128; s > 0; s >>= 1) {
            if (tid < s) red[tid] += red[tid + s];
            __syncthreads();
        }
        if (tid == 0) atomicAdd(scorePtr, red[0]);
        return;
    }

#pragma unroll
    for (int i = 0; i < 2; i++) {
#pragma unroll
        for (int rr = 0; rr < 2; rr++) {
            int row = m0 + wm * 32 + i * 16 + g + rr * 8;
            if (!actmask[row]) continue;
#pragma unroll
            for (int j = 0; j < 8; j++) {
                int c0 = n0 + wn * 64 + j * 8 + tig * 2;
                if (c0 + 1 < N) {
                    float v0 = acc[i][j][rr * 2 + 0] + bias[c0];
                    float v1 = acc[i][j][rr * 2 + 1] + bias[c0 + 1];
                    *(float2*)(C + (size_t)row * N + c0) = make_float2(v0, v1);
                } else if (c0 < N) {
                    C[(size_t)row * N + c0] = acc[i][j][rr * 2 + 0] + bias[c0];
                }
            }
        }
    }
}

// ---------------- per-token exact top-K + masked residual add ----------------
__global__ void topk_kernel() {
    int row = blockIdx.x, tid = threadIdx.x;
    __shared__ float sh[DDIM];
    __shared__ int hist[256];
    __shared__ int s_k;
    __shared__ unsigned s_pref;
    const float* hr = g_h + (size_t)row * DDIM;
    for (int j = tid; j < DDIM; j += 256) sh[j] = hr[j];
    if (tid == 0) { s_k = KTOP; s_pref = 0u; }
    __syncthreads();
    for (int shift = 24; shift >= 0; shift -= 8) {
        hist[tid] = 0;
        __syncthreads();
        unsigned pref = s_pref;
        for (int j = tid; j < DDIM; j += 256) {
            unsigned b = __float_as_uint(fabsf(sh[j]));
            bool cand = (shift == 24) || ((b >> (shift + 8)) == pref);
            if (cand) atomicAdd(&hist[(b >> shift) & 255], 1);
        }
        __syncthreads();
        if (tid == 0) {
            int k = s_k, cum = 0, d = 255;
            for (; d >= 0; --d) { cum += hist[d]; if (cum >= k) break; }
            s_k = k - (cum - hist[d]);
            s_pref = (pref << 8) | (unsigned)d;
        }
        __syncthreads();
    }
    unsigned kb = s_pref;
    if (g_active[row]) {
        float* xr = g_x + (size_t)row * DDIM;
        for (int j = tid; j < DDIM; j += 256)
            if (__float_as_uint(fabsf(sh[j])) >= kb) xr[j] += sh[j];
    }
}

__global__ void argmax_kernel() {
    if (threadIdx.x == 0) {
        int b = 0; float v = g_scores[0];
        if (g_scores[1] > v) { b = 1; v = g_scores[1]; }
        if (g_scores[2] > v) { b = 2; }
        g_best = b;
    }
}

// x += h for active rows (h holds gelu sims of best CEN branch)
__global__ void cen_add_kernel() {
    const float4* h4 = (const float4*)g_h;
    float4* x4 = (float4*)g_x;
    int tid = blockIdx.x * blockDim.x + threadIdx.x, st = gridDim.x * blockDim.x;
    for (int i = tid; i < MTOK * DDIM / 4; i += st) {
        if (g_active[i >> 8]) {
            float4 a = x4[i], b = h4[i];
            a.x += b.x; a.y += b.y; a.z += b.z; a.w += b.w;
            x4[i] = a;
        }
    }
}

// ---------------- fused VLM loss (R1 version, known-good) ----------------
__global__ __launch_bounds__(256) void vlm_kernel(
    const float* __restrict__ encW, const float* __restrict__ encb,
    const float* __restrict__ decW, const float* __restrict__ decb)
{
    __shared__ float xs[32][128];
    __shared__ float shid[32][64];
    __shared__ float red[256];
    int t0 = blockIdx.x * 32, tid = threadIdx.x;
    int sd = tid & 63, tg = tid >> 6;
    float acc[8];
#pragma unroll
    for (int u = 0; u < 8; u++) acc[u] = encb[sd];
    for (int kc = 0; kc < DDIM; kc += 128) {
        __syncthreads();
        for (int e = tid; e < 32 * 128; e += 256)
            xs[e >> 7][e & 127] = g_x[(size_t)(t0 + (e >> 7)) * DDIM + kc + (e & 127)];
        __syncthreads();
        for (int k = 0; k < 128; k++) {
            float w = encW[(size_t)(kc + k) * SDIM + sd];
#pragma unroll
            for (int u = 0; u < 8; u++) acc[u] = fmaf(xs[tg * 8 + u][k], w, acc[u]);
        }
    }
#pragma unroll
    for (int u = 0; u < 8; u++) shid[tg * 8 + u][sd] = fmaxf(acc[u], 0.f);
    __syncthreads();
    float sq = 0.f;
    for (int jj = 0; jj < 4; jj++) {
        int j = jj * 256 + tid;
        float wv[64];
#pragma unroll
        for (int s = 0; s < 64; s++) wv[s] = decW[(size_t)s * DDIM + j];
        float db = decb[j];
        for (int t = 0; t < 32; t++) {
            float r = db;
#pragma unroll
            for (int s = 0; s < 64; s++) r = fmaf(shid[t][s], wv[s], r);
            float d = r - g_x[(size_t)(t0 + t) * DDIM + j];
            sq = fmaf(d, d, sq);
        }
    }
    red[tid] = sq; __syncthreads();
    for (int s = 128; s > 0; s >>= 1) { if (tid < s) red[tid] += red[tid + s]; __syncthreads(); }
    if (tid == 0) atomicAdd(&g_vloss, (double)red[0]);
}

// ---------------- exit head confidence ----------------
__global__ void exit_kernel(const float* __restrict__ out) {
    int row = blockIdx.x;
    if (!g_active[row]) return;
    int tid = threadIdx.x;
    const float* lr = out + (size_t)row * CCLS;
    __shared__ float red[256];
    float mx = -1e30f;
    for (int j = tid; j < CCLS; j += 256) mx = fmaxf(mx, lr[j]);
    red[tid] = mx; __syncthreads();
    for (int s = 128; s > 0; s >>= 1) { if (tid < s) red[tid] = fmaxf(red[tid], red[tid + s]); __syncthreads(); }
    float m = red[0]; __syncthreads();
    float se = 0.f;
    for (int j = tid; j < CCLS; j += 256) se += expf(lr[j] - m);
    red[tid] = se; __syncthreads();
    for (int s = 128; s > 0; s >>= 1) { if (tid < s) red[tid] += red[tid + s]; __syncthreads(); }
    float conf = 1.0f / red[0];
    if (tid == 0) { g_depth[row]++; g_active[row] = (conf < THRC) ? 1 : 0; }
}

__global__ void finalize_kernel(float* __restrict__ out, int base) {
    __shared__ int red[256];
    int tid = threadIdx.x, s = 0;
    for (int i = tid; i < MTOK; i += 256) s += g_depth[i];
    red[tid] = s; __syncthreads();
    for (int w = 128; w > 0; w >>= 1) { if (tid < w) red[tid] += red[tid + w]; __syncthreads(); }
    if (tid == 0) {
        out[base + 0] = (float)red[0] / (float)MTOK;
        out[base + 1] = (float)(g_vloss / ((double)LNUM * (double)MTOK * (double)DDIM));
    }
}

extern "C" void kernel_launch(void* const* d_in, const int* in_sizes, int n_in,
                              void* d_out, int out_size) {
    const float* x = (const float*)d_in[0];
    const float* dcaW = (const float*)d_in[1];
    const float* dcab = (const float*)d_in[2];
    const float* exW = (const float*)d_in[3];
    const float* exb = (const float*)d_in[4];
    const float* cenW = (const float*)d_in[5];
    const float* cenb = (const float*)d_in[6];
    const float* cohW = (const float*)d_in[7];
    const float* encW = (const float*)d_in[9];
    const float* encb = (const float*)d_in[10];
    const float* decW = (const float*)d_in[11];
    const float* decb = (const float*)d_in[12];
    float* out = (float*)d_out;

    float *px, *ph, *pscores;
    int* pbest;
    unsigned char* pact;
    cudaGetSymbolAddress((void**)&px, g_x);
    cudaGetSymbolAddress((void**)&ph, g_h);
    cudaGetSymbolAddress((void**)&pscores, g_scores);
    cudaGetSymbolAddress((void**)&pbest, g_best);
    cudaGetSymbolAddress((void**)&pact, g_active);

    init_kernel<<<2048, 256>>>(x);

    dim3 gg(8, 128);   // both GEMMs: 128x128 tiles over 16384 x <=1024

    for (int i = 0; i < LNUM; i++) {
        // SparseDCA (flip-sensitive): scalar fp32, bitwise-R1 trajectory
        sgemm_kernel<<<gg, 256>>>(
            px, dcaW + (size_t)i * DDIM * DDIM, dcab + (size_t)i * DDIM,
            ph, MTOK, DDIM, DDIM, (const int*)0);
        topk_kernel<<<MTOK, 256>>>();

        if (i == LNUM / 2) {
            // CEN scores (flip-immune): TC, fused gelu-dot-cohW epilogue
            for (int n = 0; n < NBR; n++)
                mma_gemm<3><<<gg, 256>>>(
                    px, cenW + (size_t)n * DDIM * DDIM, cenb + (size_t)n * DDIM,
                    (float*)0, DDIM, pact, cohW, pscores + n);
            argmax_kernel<<<1, 32>>>();
            // CEN pass2 (flip-sensitive): scalar fp32, best-branch sims -> g_h
            sgemm_kernel<<<gg, 256>>>(
                px, cenW, cenb, ph, MTOK, DDIM, DDIM, pbest);
            cen_add_kernel<<<4096, 256>>>();
        }

        vlm_kernel<<<MTOK / 32, 256>>>(encW, encb, decW, decb);

        // exit head (flip-immune): TC, active rows straight into d_out
        mma_gemm<2><<<gg, 256>>>(
            px, exW + (size_t)i * DDIM * CCLS, exb + (size_t)i * CCLS,
            out, CCLS, pact, (const float*)0, (float*)0);
        exit_kernel<<<MTOK, 256>>>(out);
    }

    finalize_kernel<<<1, 256>>>(out, out_size - 2);
}